// round 6
// baseline (speedup 1.0000x reference)
#include <cuda_runtime.h>

// ---------------------------------------------------------------------------
// Fused MLP, packed-f32x2, 2 rows/thread (weight-load amortization).
//   a1 = lrelu(a @ Wa + ba)        [B,45] -> [B,68]
//   b1 = lrelu(b @ Wb + bb)        [B,102] -> [B,68]
//   c  = concat(a1, b1, meta)      [B,140]
//   10 x (c = lrelu(c @ Wi + Bi))  140->34->34->20->20->20->20->20->5->2->1
//
// Each thread computes rows t and t+B/2: every weight load from SMEM feeds
// both rows (4 FFMA2 per 16B LDS instead of 2), halving smem-crossbar
// pressure — the binding resource in the previous kernel (L1=69.6%).
// Tower GEMVs are column-chunked into 36-wide halves (Wa/Wb padded to 72
// cols, zero-filled) so the 68-wide tower accumulator is never fully live;
// pad columns activate to exactly 0 so their consume contributes 0.
// Fused activation-consume: finished accumulator pairs are lrelu'd and
// immediately folded into the next layer's accumulator.
// ---------------------------------------------------------------------------

#define NTHREADS 320

using ull = unsigned long long;

// SMEM layout (float offsets; all multiples of 4 -> 16B-aligned rows)
constexpr int OF_Wa = 0;                 // 45*72  = 3240 (cols padded 68->72)
constexpr int OF_ba = OF_Wa + 3240;      // 72
constexpr int OF_Wb = OF_ba + 72;        // 102*72 = 7344
constexpr int OF_bb = OF_Wb + 7344;      // 72
constexpr int OF_W0 = OF_bb + 72;        // 140*36 = 5040
constexpr int OF_B0 = OF_W0 + 5040;      // 36
constexpr int OF_W1 = OF_B0 + 36;        // 34*36  = 1224
constexpr int OF_B1 = OF_W1 + 1224;      // 36
constexpr int OF_W2 = OF_B1 + 36;        // 34*20  = 680
constexpr int OF_B2 = OF_W2 + 680;       // 20
constexpr int OF_W3 = OF_B2 + 20;        // 400
constexpr int OF_B3 = OF_W3 + 400;       // 20
constexpr int OF_W4 = OF_B3 + 20;        // 400
constexpr int OF_B4 = OF_W4 + 400;       // 20
constexpr int OF_W5 = OF_B4 + 20;        // 400
constexpr int OF_B5 = OF_W5 + 400;       // 20
constexpr int OF_W6 = OF_B5 + 20;        // 400
constexpr int OF_B6 = OF_W6 + 400;       // 20
constexpr int OF_W7 = OF_B6 + 20;        // 20*8 = 160
constexpr int OF_B7 = OF_W7 + 160;       // 8
constexpr int OF_W8 = OF_B7 + 8;         // 8*4 = 32 (K padded 5->8)
constexpr int OF_B8 = OF_W8 + 32;        // 4
constexpr int OF_W9 = OF_B8 + 4;         // 4*4 = 16 (K padded 2->4)
constexpr int OF_B9 = OF_W9 + 16;        // 4
constexpr int SMEM_FLOATS = OF_B9 + 4;   // 19668
constexpr int SMEM_BYTES  = SMEM_FLOATS * 4;   // 78672

struct Params {
    const float* p[27];
};

// ---- packed f32x2 helpers ----
__device__ __forceinline__ ull pack2(float x) {
    ull r;
    asm("mov.b64 %0, {%1, %1};" : "=l"(r) : "f"(x));
    return r;
}
__device__ __forceinline__ void unpack2(ull v, float& lo, float& hi) {
    asm("mov.b64 {%0, %1}, %2;" : "=f"(lo), "=f"(hi) : "l"(v));
}
__device__ __forceinline__ ull fma2(ull a, ull b, ull c) {
    ull d;
    asm("fma.rn.f32x2 %0, %1, %2, %3;" : "=l"(d) : "l"(a), "l"(b), "l"(c));
    return d;
}
__device__ __forceinline__ float lrelu1(float x) {
    return x > 0.0f ? x : 0.01f * x;
}

// ---- cooperative weight staging (N-padded + K-padded, zero-filled) ----
__device__ __forceinline__ void load_mat(float* __restrict__ dst,
                                         const float* __restrict__ src,
                                         int din, int dout, int dpad, int kpad) {
    for (int i = threadIdx.x; i < kpad * dpad; i += NTHREADS) {
        int r = i / dpad;
        int c = i - r * dpad;
        dst[i] = (r < din && c < dout) ? src[r * dout + c] : 0.0f;
    }
}
__device__ __forceinline__ void load_vec(float* __restrict__ dst,
                                         const float* __restrict__ src,
                                         int n, int npad) {
    for (int i = threadIdx.x; i < npad; i += NTHREADS) {
        dst[i] = (i < n) ? src[i] : 0.0f;
    }
}

// Dual-row fma: ONE 16B weight load feeds both rows (4 FFMA2 per LDS.128).
template <int NP>
__device__ __forceinline__ void rowfma_d(ull xv0, ull xv1,
                                         const float* __restrict__ w,
                                         ull* __restrict__ a0,
                                         ull* __restrict__ a1) {
    const ulonglong2* wr = reinterpret_cast<const ulonglong2*>(w);
#pragma unroll
    for (int j = 0; j < NP / 4; ++j) {
        const ulonglong2 wv = wr[j];
        a0[2 * j + 0] = fma2(xv0, wv.x, a0[2 * j + 0]);
        a0[2 * j + 1] = fma2(xv0, wv.y, a0[2 * j + 1]);
        a1[2 * j + 0] = fma2(xv1, wv.x, a1[2 * j + 0]);
        a1[2 * j + 1] = fma2(xv1, wv.y, a1[2 * j + 1]);
    }
}

// Dual GEMV step over K inputs; W row stride = STRIDE floats.
template <int K, int NP, int STRIDE>
__device__ __forceinline__ void gemv_d(const float* __restrict__ x0,
                                       const float* __restrict__ x1,
                                       const float* __restrict__ w,
                                       ull* __restrict__ a0,
                                       ull* __restrict__ a1) {
#pragma unroll
    for (int k = 0; k < K; ++k)
        rowfma_d<NP>(pack2(x0[k]), pack2(x1[k]), w + k * STRIDE, a0, a1);
}

template <int NP>
__device__ __forceinline__ void init_bias_d(ull* __restrict__ a0,
                                            ull* __restrict__ a1,
                                            const float* __restrict__ b) {
    const ull* bp = reinterpret_cast<const ull*>(b);
#pragma unroll
    for (int j = 0; j < NP / 2; ++j) { a0[j] = bp[j]; a1[j] = bp[j]; }
}

// Fused dual consume: one finished pair per row -> lrelu -> fold into next
// layer's accumulators via 2 consecutive weight rows (w, w+NP).
template <int NP>
__device__ __forceinline__ void consume_d(ull av0, ull av1,
                                          const float* __restrict__ w,
                                          ull* __restrict__ a0,
                                          ull* __restrict__ a1) {
    float l0, h0, l1, h1;
    unpack2(av0, l0, h0);
    unpack2(av1, l1, h1);
    rowfma_d<NP>(pack2(lrelu1(l0)), pack2(lrelu1(l1)), w, a0, a1);
    rowfma_d<NP>(pack2(lrelu1(h0)), pack2(lrelu1(h1)), w + NP, a0, a1);
}

__global__ __launch_bounds__(NTHREADS, 1)
void mlp_fused_kernel(Params prm, float* __restrict__ out, int half) {
    extern __shared__ float sw[];

    // ---- stage all weights into SMEM (padded) ----
    load_mat(sw + OF_Wa, prm.p[3], 45, 68, 72, 45);
    load_vec(sw + OF_ba, prm.p[4], 68, 72);
    load_mat(sw + OF_Wb, prm.p[5], 102, 68, 72, 102);
    load_vec(sw + OF_bb, prm.p[6], 68, 72);
    load_mat(sw + OF_W0, prm.p[7], 140, 34, 36, 140);
    load_vec(sw + OF_B0, prm.p[8], 34, 36);
    load_mat(sw + OF_W1, prm.p[9], 34, 34, 36, 34);
    load_vec(sw + OF_B1, prm.p[10], 34, 36);
    load_mat(sw + OF_W2, prm.p[11], 34, 20, 20, 34);
    load_vec(sw + OF_B2, prm.p[12], 20, 20);
    load_mat(sw + OF_W3, prm.p[13], 20, 20, 20, 20);
    load_vec(sw + OF_B3, prm.p[14], 20, 20);
    load_mat(sw + OF_W4, prm.p[15], 20, 20, 20, 20);
    load_vec(sw + OF_B4, prm.p[16], 20, 20);
    load_mat(sw + OF_W5, prm.p[17], 20, 20, 20, 20);
    load_vec(sw + OF_B5, prm.p[18], 20, 20);
    load_mat(sw + OF_W6, prm.p[19], 20, 20, 20, 20);
    load_vec(sw + OF_B6, prm.p[20], 20, 20);
    load_mat(sw + OF_W7, prm.p[21], 20, 5, 8, 20);
    load_vec(sw + OF_B7, prm.p[22], 5, 8);
    load_mat(sw + OF_W8, prm.p[23], 5, 2, 4, 8);    // K padded 5->8
    load_vec(sw + OF_B8, prm.p[24], 2, 4);
    load_mat(sw + OF_W9, prm.p[25], 2, 1, 4, 4);    // K padded 2->4
    load_vec(sw + OF_B9, prm.p[26], 1, 4);
    __syncthreads();

    const int row0 = blockIdx.x * NTHREADS + threadIdx.x;
    if (row0 >= half) return;
    const int row1 = row0 + half;

    const float* __restrict__ A0 = prm.p[0] + (long)row0 * 45;
    const float* __restrict__ A1 = prm.p[0] + (long)row1 * 45;
    const float* __restrict__ Bq0 = prm.p[1] + (long)row0 * 102;
    const float* __restrict__ Bq1 = prm.p[1] + (long)row1 * 102;
    const float* __restrict__ Mt0 = prm.p[2] + (long)row0 * 4;
    const float* __restrict__ Mt1 = prm.p[2] + (long)row1 * 4;

    // layer-0 accumulators (one per row), live across both towers
    ull h0a[18], h0b[18];
    init_bias_d<36>(h0a, h0b, sw + OF_B0);

    // ---- tower A: column chunks of 36 (Wa padded to 72 cols) ----
#pragma unroll
    for (int cc = 0; cc < 2; ++cc) {
        ull t0[18], t1[18];
        init_bias_d<36>(t0, t1, sw + OF_ba + cc * 36);
        {
            float xa0[9], xa1[9];
#pragma unroll
            for (int c = 0; c < 5; ++c) {
#pragma unroll
                for (int k = 0; k < 9; ++k) {
                    xa0[k] = A0[c * 9 + k];
                    xa1[k] = A1[c * 9 + k];
                }
                gemv_d<9, 36, 72>(xa0, xa1,
                                  sw + OF_Wa + (c * 9) * 72 + cc * 36, t0, t1);
            }
        }
        // consume: a1 cols cc*36 + (2j,2j+1) -> W0 rows cc*36 + 2j
        // (cc=1 pairs 16,17 are pad cols 68..71: activation exactly 0)
#pragma unroll
        for (int j = 0; j < 18; ++j)
            consume_d<36>(t0[j], t1[j],
                          sw + OF_W0 + (cc * 36 + 2 * j) * 36, h0a, h0b);
    }

    // ---- tower B: column chunks of 36 (Wb padded to 72 cols) ----
#pragma unroll
    for (int cc = 0; cc < 2; ++cc) {
        ull t0[18], t1[18];
        init_bias_d<36>(t0, t1, sw + OF_bb + cc * 36);
        {
            float xb0[6], xb1[6];
#pragma unroll
            for (int c = 0; c < 17; ++c) {
#pragma unroll
                for (int k = 0; k < 6; ++k) {
                    xb0[k] = Bq0[c * 6 + k];
                    xb1[k] = Bq1[c * 6 + k];
                }
                gemv_d<6, 36, 72>(xb0, xb1,
                                  sw + OF_Wb + (c * 6) * 72 + cc * 36, t0, t1);
            }
        }
        // b1 cols cc*36+2j -> W0 rows 68 + cc*36 + 2j
        // (cc=1 pairs 16,17 are pad cols: activation exactly 0 -> rows 136..139 untouched)
#pragma unroll
        for (int j = 0; j < 18; ++j)
            consume_d<36>(t0[j], t1[j],
                          sw + OF_W0 + (68 + cc * 36 + 2 * j) * 36, h0a, h0b);
    }

    // ---- meta rows 136..139 of W0 (no activation on meta) ----
    {
        float xm0[4], xm1[4];
#pragma unroll
        for (int k = 0; k < 4; ++k) { xm0[k] = Mt0[k]; xm1[k] = Mt1[k]; }
        gemv_d<4, 36, 36>(xm0, xm1, sw + OF_W0 + 136 * 36, h0a, h0b);
    }

    // ---- layer 1: 34 -> 34 (pairs 0..16 real; pair 17 is pad) ----
    ull aA0[18], aA1[18];
    init_bias_d<36>(aA0, aA1, sw + OF_B1);
#pragma unroll
    for (int j = 0; j < 17; ++j)
        consume_d<36>(h0a[j], h0b[j], sw + OF_W1 + (2 * j) * 36, aA0, aA1);

    // ---- layer 2: 34 -> 20 ----
    ull c20a0[10], c20a1[10];
    init_bias_d<20>(c20a0, c20a1, sw + OF_B2);
#pragma unroll
    for (int j = 0; j < 17; ++j)
        consume_d<20>(aA0[j], aA1[j], sw + OF_W2 + (2 * j) * 20, c20a0, c20a1);

    // ---- layers 3..6: 20 -> 20, ping-pong ----
    ull c20b0[10], c20b1[10];
    init_bias_d<20>(c20b0, c20b1, sw + OF_B3);
#pragma unroll
    for (int j = 0; j < 10; ++j)
        consume_d<20>(c20a0[j], c20a1[j], sw + OF_W3 + (2 * j) * 20, c20b0, c20b1);

    init_bias_d<20>(c20a0, c20a1, sw + OF_B4);
#pragma unroll
    for (int j = 0; j < 10; ++j)
        consume_d<20>(c20b0[j], c20b1[j], sw + OF_W4 + (2 * j) * 20, c20a0, c20a1);

    init_bias_d<20>(c20b0, c20b1, sw + OF_B5);
#pragma unroll
    for (int j = 0; j < 10; ++j)
        consume_d<20>(c20a0[j], c20a1[j], sw + OF_W5 + (2 * j) * 20, c20b0, c20b1);

    init_bias_d<20>(c20a0, c20a1, sw + OF_B6);
#pragma unroll
    for (int j = 0; j < 10; ++j)
        consume_d<20>(c20b0[j], c20b1[j], sw + OF_W6 + (2 * j) * 20, c20a0, c20a1);

    // ---- layer 7: 20 -> 5 (pad 8) ----
    ull a80[4], a81[4];
    init_bias_d<8>(a80, a81, sw + OF_B7);
#pragma unroll
    for (int j = 0; j < 10; ++j)
        consume_d<8>(c20a0[j], c20a1[j], sw + OF_W7 + (2 * j) * 8, a80, a81);

    // ---- layer 8: 5 -> 2 (pad 4; W8 K-padded to 8 rows) ----
    ull a40[2], a41[2];
    init_bias_d<4>(a40, a41, sw + OF_B8);
#pragma unroll
    for (int j = 0; j < 4; ++j)
        consume_d<4>(a80[j], a81[j], sw + OF_W8 + (2 * j) * 4, a40, a41);

    // ---- layer 9: 2 -> 1 (pad 4; W9 K-padded to 4 rows) ----
    ull f0[2], f1[2];
    init_bias_d<4>(f0, f1, sw + OF_B9);
#pragma unroll
    for (int j = 0; j < 2; ++j)
        consume_d<4>(a40[j], a41[j], sw + OF_W9 + (2 * j) * 4, f0, f1);

    float lo0, hi0, lo1, hi1;
    unpack2(f0[0], lo0, hi0);
    unpack2(f1[0], lo1, hi1);
    out[row0] = lrelu1(lo0);
    out[row1] = lrelu1(lo1);
}

extern "C" void kernel_launch(void* const* d_in, const int* in_sizes, int n_in,
                              void* d_out, int out_size) {
    Params prm;
    for (int i = 0; i < 27; ++i) prm.p[i] = (const float*)d_in[i];
    const int nrows = in_sizes[0] / 45;
    const int half = nrows / 2;   // B is even (262144)

    cudaFuncSetAttribute(mlp_fused_kernel,
                         cudaFuncAttributeMaxDynamicSharedMemorySize,
                         SMEM_BYTES);

    const int grid = (half + NTHREADS - 1) / NTHREADS;
    mlp_fused_kernel<<<grid, NTHREADS, SMEM_BYTES>>>(prm, (float*)d_out, half);
}